// round 17
// baseline (speedup 1.0000x reference)
#include <cuda_runtime.h>
#include <cuda_bf16.h>
#include <cstdint>

#define DI __device__ __forceinline__

#define HID   256
#define KP1   320        // word dim 300 padded to 320
#define KF    1024       // fused 2-level K
#define MLEAF 262144
#define VOCAB 50257
#define VPAD  50304      // 393 * 128
#define TPB   256

// ---- shared memory: 3-stage pipeline, K-chunk 32 bf16 (64B rows) ----
#define SM_IDS   0                          // up to 512 ints
#define SM_STAGE 2048
#define STG_SZ   32768
#define PL_SZ    8192
#define SMEM_SZ  (SM_STAGE + 3 * STG_SZ)    // 100352 B -> 2 CTAs/SM

// ---- static device scratch (no allocation allowed) ----
__device__ __align__(256) __nv_bfloat16 g_w1h[HID * KP1];
__device__ __align__(256) __nv_bfloat16 g_w1l[HID * KP1];
__device__ __align__(256) __nv_bfloat16 g_w2ah[512 * HID];  // W2 A-layout [512,256]
__device__ __align__(256) __nv_bfloat16 g_w2al[512 * HID];
__device__ __align__(256) __nv_bfloat16 g_w2th[HID * 512];  // W2^T B-layout [256,512]
__device__ __align__(256) __nv_bfloat16 g_w2tl[HID * 512];
__device__ __align__(256) __nv_bfloat16 g_w4ah[KF * HID];   // W4 A-layout [1024,256]
__device__ __align__(256) __nv_bfloat16 g_w4al[KF * HID];
__device__ __align__(256) __nv_bfloat16 g_w4h[HID * KF];    // W4 B-layout [256,1024]
__device__ __align__(256) __nv_bfloat16 g_w4l[HID * KF];
__device__ float g_b4[HID];
__device__ float g_bz[HID];                                 // zero bias (static init)
__device__ __align__(256) __nv_bfloat16 g_eh[(size_t)VPAD * KP1];
__device__ __align__(256) __nv_bfloat16 g_el[(size_t)VPAD * KP1];
__device__ __align__(256) __nv_bfloat16 g_Th[(size_t)VPAD * HID];   // T = E*W1+b1
__device__ __align__(256) __nv_bfloat16 g_Tl[(size_t)VPAD * HID];
__device__ __align__(256) __nv_bfloat16 g_p0h[(size_t)(MLEAF / 4) * HID];
__device__ __align__(256) __nv_bfloat16 g_p0l[(size_t)(MLEAF / 4) * HID];
__device__ __align__(256) __nv_bfloat16 g_p1h[(size_t)(MLEAF / 16) * HID];
__device__ __align__(256) __nv_bfloat16 g_p1l[(size_t)(MLEAF / 16) * HID];

// ---------------- PTX helpers (compute_103-safe ISA only) ----------------
DI uint32_t smem_u32(const void* p) {
    uint32_t a;
    asm("{ .reg .u64 t; cvta.to.shared.u64 t, %1; cvt.u32.u64 %0, t; }" : "=r"(a) : "l"(p));
    return a;
}

#define CPA16(dst, src) \
    asm volatile("cp.async.cg.shared.global [%0], [%1], 16;" :: "r"(dst), "l"(src))
#define CPA_COMMIT() \
    asm volatile("cp.async.commit_group;" ::: "memory")
#define CPA_WAIT(n) \
    asm volatile("cp.async.wait_group %0;" :: "n"(n) : "memory")

#define LDSM4(r0, r1, r2, r3, addr)                                            \
    asm volatile("ldmatrix.sync.aligned.m8n8.x4.shared.b16 {%0,%1,%2,%3}, [%4];" \
                 : "=r"(r0), "=r"(r1), "=r"(r2), "=r"(r3) : "r"(addr))

#define MMA16816(d, a, b0, b1)                                                 \
    asm volatile("mma.sync.aligned.m16n8k16.row.col.f32.bf16.bf16.f32 "        \
                 "{%0,%1,%2,%3}, {%4,%5,%6,%7}, {%8,%9}, {%0,%1,%2,%3};"       \
                 : "+f"((d)[0]), "+f"((d)[1]), "+f"((d)[2]), "+f"((d)[3])      \
                 : "r"((a)[0]), "r"((a)[1]), "r"((a)[2]), "r"((a)[3]),         \
                   "r"(b0), "r"(b1))

DI void split2(float v, __nv_bfloat16& h, __nv_bfloat16& l) {
    h = __float2bfloat16(v);
    l = __float2bfloat16(v - __bfloat162float(h));
}

// 64B-row swizzle: XOR col16 bits[4:5] with row byte bits[7:8]
DI uint32_t sw64(uint32_t off) { return off ^ ((off >> 3) & 0x30); }

// ---------------- prep: split W1 transposed + padded (B-layout) ----------------
__global__ void prep_w1(const float* __restrict__ W1) {
    int i = blockIdx.x * blockDim.x + threadIdx.x;
    if (i >= HID * KP1) return;
    int n = i / KP1, k = i % KP1;
    float v = (k < 300) ? W1[k * HID + n] : 0.0f;
    __nv_bfloat16 h, l;
    split2(v, h, l);
    g_w1h[i] = h; g_w1l[i] = l;
}

// ---------------- prep: split W2 in BOTH layouts ----------------
__global__ void prep_w2(const float* __restrict__ W2) {
    int i = blockIdx.x * blockDim.x + threadIdx.x;
    if (i >= 512 * HID) return;
    int k = i / HID, n = i % HID;
    __nv_bfloat16 h, l;
    split2(W2[i], h, l);
    g_w2ah[i] = h;            g_w2al[i] = l;             // A-layout [k][n]
    g_w2th[n * 512 + k] = h;  g_w2tl[n * 512 + k] = l;   // B-layout [n][k]
}

// ---------------- prep: transpose W4 A-layout -> B-layout ----------------
__global__ void transpose_w4() {
    int i = blockIdx.x * blockDim.x + threadIdx.x;
    if (i >= KF * HID) return;
    int k = i / HID, n = i % HID;
    g_w4h[n * KF + k] = g_w4ah[i];
    g_w4l[n * KF + k] = g_w4al[i];
}

// ---------------- prep: fused bias b4 = b2@(W2top+W2bot) + b2 ----------------
__global__ void prep_b4(const float* __restrict__ W2, const float* __restrict__ b2) {
    int n = threadIdx.x;     // 1 block, 256 threads
    float s = b2[n];
    for (int j = 0; j < 256; j++)
        s += b2[j] * (W2[(size_t)j * HID + n] + W2[(size_t)(256 + j) * HID + n]);
    g_b4[n] = s;
}

// ---------------- prep: split embedding table (padded rows/cols) ----------------
__global__ void prep_emb(const float* __restrict__ E) {
    size_t i = (size_t)blockIdx.x * blockDim.x + threadIdx.x;
    if (i >= (size_t)VPAD * KP1) return;
    int v = (int)(i / KP1), k = (int)(i % KP1);
    float x = (v < VOCAB && k < 300) ? E[(size_t)v * 300 + k] : 0.0f;
    __nv_bfloat16 h, l;
    split2(x, h, l);
    g_eh[i] = h; g_el[i] = l;
}

// ---------------- GEMM: Out[128,128] = A[128,KPAD] @ B[128-slice,KPAD]^T + bias -
// Split-bf16 3-MMA (hh + hl + lh), 3-stage cp.async pipeline, K-chunk 32.
// MODE 0: A row r = Ah/Al[(m0+r)*KPAD + k]; B row stride = bstride elements.
// MODE 1: A row r = concat(T[ids[4r]],..,T[ids[4r+3]]), KPAD=1024, T stride HID
template <int MODE, int KPAD, int FINAL>
__global__ void __launch_bounds__(TPB, 2) gemm_kernel(
    const int* __restrict__ ids,
    const __nv_bfloat16* __restrict__ Ah, const __nv_bfloat16* __restrict__ Al,
    const __nv_bfloat16* __restrict__ Bh, const __nv_bfloat16* __restrict__ Bl,
    const float* __restrict__ bias,
    __nv_bfloat16* __restrict__ Oh, __nv_bfloat16* __restrict__ Ol,
    float* __restrict__ Of, int bstride)
{
    extern __shared__ char smem[];
    const int tid = threadIdx.x, wid = tid >> 5, lid = tid & 31;
    const int m0 = blockIdx.x * 128, n0 = blockIdx.y * 128;
    const int wm = wid >> 2, wn = wid & 3;              // 2 x 4 warp grid
    int* sids = (int*)smem;

    if (MODE == 1) {
        sids[tid] = ids[m0 * 4 + tid];
        sids[tid + 256] = ids[m0 * 4 + 256 + tid];
    }
    __syncthreads();

    const uint32_t s_base = smem_u32(smem + SM_STAGE);
    const int NCH = KPAD / 32;

    // loader: all cp.async for chunk ch into stage st
    auto load_chunk = [&](int ch, int st) {
        const uint32_t stg = s_base + (uint32_t)st * STG_SZ;
        #pragma unroll
        for (int v = tid; v < 512; v += TPB) {           // A hi + A lo
            int r = v >> 2, u = v & 3;
            size_t off;
            if (MODE == 1) {
                int id = sids[4 * r + (ch >> 3)];        // 8 chunks per T row
                off = (size_t)id * (HID * 2) + (size_t)((ch & 7) * 64 + u * 16);
            } else {
                off = (size_t)(m0 + r) * (KPAD * 2) + (size_t)(ch * 64 + u * 16);
            }
            uint32_t d = sw64((uint32_t)(r * 64 + u * 16));
            CPA16(stg + d,         (const char*)Ah + off);
            CPA16(stg + PL_SZ + d, (const char*)Al + off);
        }
        #pragma unroll
        for (int v = tid; v < 512; v += TPB) {           // B hi + B lo
            int r = v >> 2, u = v & 3;
            size_t off = (size_t)(n0 + r) * ((size_t)bstride * 2) + (size_t)(ch * 64 + u * 16);
            uint32_t d = sw64((uint32_t)(r * 64 + u * 16));
            CPA16(stg + 2 * PL_SZ + d, (const char*)Bh + off);
            CPA16(stg + 3 * PL_SZ + d, (const char*)Bl + off);
        }
        CPA_COMMIT();
    };

    float acc[4][4][4];
    #pragma unroll
    for (int i = 0; i < 4; i++)
        #pragma unroll
        for (int j = 0; j < 4; j++)
            #pragma unroll
            for (int c = 0; c < 4; c++) acc[i][j][c] = 0.0f;

    load_chunk(0, 0);
    load_chunk(1, 1);

    for (int ch = 0; ch < NCH; ch++) {
        if (ch == NCH - 1) { CPA_WAIT(0); } else { CPA_WAIT(1); }
        __syncthreads();   // chunk ch ready; stage (ch+2)%3's old data fully consumed
        if (ch + 2 < NCH) load_chunk(ch + 2, (ch + 2) % 3);

        const uint32_t stg = s_base + (uint32_t)(ch % 3) * STG_SZ;
        const uint32_t s_ahi = stg, s_alo = stg + PL_SZ;
        const uint32_t s_bhi = stg + 2 * PL_SZ, s_blo = stg + 3 * PL_SZ;

        #pragma unroll
        for (int ks = 0; ks < 2; ks++) {
            uint32_t a[4][4], bh[4][2], bl[4][2];

            #pragma unroll
            for (int i = 0; i < 4; i++) {
                int row = wm * 64 + i * 16 + (lid & 15);
                int col = ks * 2 + (lid >> 4);
                LDSM4(a[i][0], a[i][1], a[i][2], a[i][3],
                      s_ahi + sw64(row * 64 + (col << 4)));
            }
            #pragma unroll
            for (int p = 0; p < 2; p++) {
                int row = wn * 32 + p * 16 + ((lid & 7) + ((lid >> 4) << 3));
                int col = ks * 2 + ((lid >> 3) & 1);
                LDSM4(bh[2 * p][0], bh[2 * p][1], bh[2 * p + 1][0], bh[2 * p + 1][1],
                      s_bhi + sw64(row * 64 + (col << 4)));
            }
            // pass 1: A_hi x B_hi
            #pragma unroll
            for (int i = 0; i < 4; i++)
                #pragma unroll
                for (int j = 0; j < 4; j++)
                    MMA16816(acc[i][j], a[i], bh[j][0], bh[j][1]);

            #pragma unroll
            for (int p = 0; p < 2; p++) {
                int row = wn * 32 + p * 16 + ((lid & 7) + ((lid >> 4) << 3));
                int col = ks * 2 + ((lid >> 3) & 1);
                LDSM4(bl[2 * p][0], bl[2 * p][1], bl[2 * p + 1][0], bl[2 * p + 1][1],
                      s_blo + sw64(row * 64 + (col << 4)));
            }
            // pass 2: A_hi x B_lo
            #pragma unroll
            for (int i = 0; i < 4; i++)
                #pragma unroll
                for (int j = 0; j < 4; j++)
                    MMA16816(acc[i][j], a[i], bl[j][0], bl[j][1]);

            #pragma unroll
            for (int i = 0; i < 4; i++) {
                int row = wm * 64 + i * 16 + (lid & 15);
                int col = ks * 2 + (lid >> 4);
                LDSM4(a[i][0], a[i][1], a[i][2], a[i][3],
                      s_alo + sw64(row * 64 + (col << 4)));
            }
            // pass 3: A_lo x B_hi
            #pragma unroll
            for (int i = 0; i < 4; i++)
                #pragma unroll
                for (int j = 0; j < 4; j++)
                    MMA16816(acc[i][j], a[i], bh[j][0], bh[j][1]);
        }
    }

    // ---- epilogue: +bias, write fp32 (final) or split bf16 planes ----
    #pragma unroll
    for (int i = 0; i < 4; i++) {
        int r0 = m0 + wm * 64 + i * 16 + (lid >> 2);
        #pragma unroll
        for (int j = 0; j < 4; j++) {
            int gc = n0 + wn * 32 + j * 8 + 2 * (lid & 3);
            float b0 = bias[gc], b1 = bias[gc + 1];
            float v00 = acc[i][j][0] + b0, v01 = acc[i][j][1] + b1;
            float v10 = acc[i][j][2] + b0, v11 = acc[i][j][3] + b1;
            if (FINAL) {
                *(float2*)(Of + (size_t)r0 * HID + gc)        = make_float2(v00, v01);
                *(float2*)(Of + (size_t)(r0 + 8) * HID + gc)  = make_float2(v10, v11);
            } else {
                __nv_bfloat16 h0, l0, h1, l1;
                split2(v00, h0, l0); split2(v01, h1, l1);
                union { __nv_bfloat16 b[2]; uint32_t u; } ph, pl;
                ph.b[0] = h0; ph.b[1] = h1; pl.b[0] = l0; pl.b[1] = l1;
                *(uint32_t*)(Oh + (size_t)r0 * HID + gc) = ph.u;
                *(uint32_t*)(Ol + (size_t)r0 * HID + gc) = pl.u;
                split2(v10, h0, l0); split2(v11, h1, l1);
                ph.b[0] = h0; ph.b[1] = h1; pl.b[0] = l0; pl.b[1] = l1;
                *(uint32_t*)(Oh + (size_t)(r0 + 8) * HID + gc) = ph.u;
                *(uint32_t*)(Ol + (size_t)(r0 + 8) * HID + gc) = pl.u;
            }
        }
    }
}

// ---------------- driver ----------------
extern "C" void kernel_launch(void* const* d_in, const int* in_sizes, int n_in,
                              void* d_out, int out_size) {
    const int*   ids = (const int*)d_in[0];
    const float* emb = (const float*)d_in[1];
    const float* W1  = (const float*)d_in[2];
    const float* b1  = (const float*)d_in[3];
    const float* W2  = (const float*)d_in[4];
    const float* b2  = (const float*)d_in[5];
    float* out = (float*)d_out;

    __nv_bfloat16 *w1h, *w1l, *w2ah, *w2al, *w2th, *w2tl;
    __nv_bfloat16 *w4ah, *w4al, *w4h, *w4l, *eh, *el, *th, *tl, *p0h, *p0l, *p1h, *p1l;
    float *b4, *bz;
    cudaGetSymbolAddress((void**)&w1h,  g_w1h);
    cudaGetSymbolAddress((void**)&w1l,  g_w1l);
    cudaGetSymbolAddress((void**)&w2ah, g_w2ah);
    cudaGetSymbolAddress((void**)&w2al, g_w2al);
    cudaGetSymbolAddress((void**)&w2th, g_w2th);
    cudaGetSymbolAddress((void**)&w2tl, g_w2tl);
    cudaGetSymbolAddress((void**)&w4ah, g_w4ah);
    cudaGetSymbolAddress((void**)&w4al, g_w4al);
    cudaGetSymbolAddress((void**)&w4h,  g_w4h);
    cudaGetSymbolAddress((void**)&w4l,  g_w4l);
    cudaGetSymbolAddress((void**)&b4,   g_b4);
    cudaGetSymbolAddress((void**)&bz,   g_bz);
    cudaGetSymbolAddress((void**)&eh,   g_eh);
    cudaGetSymbolAddress((void**)&el,   g_el);
    cudaGetSymbolAddress((void**)&th,   g_Th);
    cudaGetSymbolAddress((void**)&tl,   g_Tl);
    cudaGetSymbolAddress((void**)&p0h,  g_p0h);
    cudaGetSymbolAddress((void**)&p0l,  g_p0l);
    cudaGetSymbolAddress((void**)&p1h,  g_p1h);
    cudaGetSymbolAddress((void**)&p1l,  g_p1l);

    cudaFuncSetAttribute(gemm_kernel<0, 256, 0>, cudaFuncAttributeMaxDynamicSharedMemorySize, SMEM_SZ);
    cudaFuncSetAttribute(gemm_kernel<0, KP1, 0>, cudaFuncAttributeMaxDynamicSharedMemorySize, SMEM_SZ);
    cudaFuncSetAttribute(gemm_kernel<1, KF, 0>,  cudaFuncAttributeMaxDynamicSharedMemorySize, SMEM_SZ);
    cudaFuncSetAttribute(gemm_kernel<0, KF, 0>,  cudaFuncAttributeMaxDynamicSharedMemorySize, SMEM_SZ);
    cudaFuncSetAttribute(gemm_kernel<0, KF, 1>,  cudaFuncAttributeMaxDynamicSharedMemorySize, SMEM_SZ);

    // ---- weight/bias/embedding prep ----
    prep_w1<<<(HID * KP1 + 255) / 256, 256>>>(W1);
    prep_w2<<<(512 * HID + 255) / 256, 256>>>(W2);
    {
        size_t n = (size_t)VPAD * KP1;
        prep_emb<<<(int)((n + 255) / 256), 256>>>(emb);
    }
    // W4 = [[W2@W2top];[W2@W2bot]] via split-GEMM compose (A-layout split out)
    gemm_kernel<0, 256, 0><<<dim3(4, 2), TPB, SMEM_SZ>>>(
        nullptr, w2ah, w2al, w2th, w2tl, bz, w4ah, w4al, nullptr, 512);
    gemm_kernel<0, 256, 0><<<dim3(4, 2), TPB, SMEM_SZ>>>(
        nullptr, w2ah, w2al, w2th + 256, w2tl + 256, bz,
        w4ah + 512 * HID, w4al + 512 * HID, nullptr, 512);
    transpose_w4<<<(KF * HID + 255) / 256, 256>>>();
    prep_b4<<<1, 256>>>(W2, b2);

    // T = E @ W1t + b1 over padded vocab -> split planes [VPAD, 256]
    gemm_kernel<0, KP1, 0><<<dim3(VPAD / 128, 2), TPB, SMEM_SZ>>>(
        nullptr, eh, el, w1h, w1l, b1, th, tl, nullptr, KP1);

    // levels 1+2 fused: A row r = concat T[ids[4r..4r+3]] -> p0 [65536, 256]
    gemm_kernel<1, KF, 0><<<dim3((MLEAF / 4) / 128, 2), TPB, SMEM_SZ>>>(
        ids, th, tl, w4h, w4l, b4, p0h, p0l, nullptr, KF);

    // levels 3+4: view p0 [65536,256] as [16384,1024] -> p1 [16384, 256]
    gemm_kernel<0, KF, 0><<<dim3((MLEAF / 16) / 128, 2), TPB, SMEM_SZ>>>(
        nullptr, p0h, p0l, w4h, w4l, b4, p1h, p1l, nullptr, KF);

    // levels 5+6: [16384,256] -> [4096,1024] -> p0 [4096, 256]
    gemm_kernel<0, KF, 0><<<dim3(4096 / 128, 2), TPB, SMEM_SZ>>>(
        nullptr, p1h, p1l, w4h, w4l, b4, p0h, p0l, nullptr, KF);

    // levels 7+8: [4096,256] -> [1024,1024] -> p1 [1024, 256]
    gemm_kernel<0, KF, 0><<<dim3(1024 / 128, 2), TPB, SMEM_SZ>>>(
        nullptr, p0h, p0l, w4h, w4l, b4, p1h, p1l, nullptr, KF);

    // levels 9+10: [1024,256] -> [256,1024] -> out fp32 [256, 256]
    gemm_kernel<0, KF, 1><<<dim3(256 / 128, 2), TPB, SMEM_SZ>>>(
        nullptr, p1h, p1l, w4h, w4l, b4, nullptr, nullptr, out, KF);
}